// round 6
// baseline (speedup 1.0000x reference)
#include <cuda_runtime.h>
#include <cstdint>

#define NNODES 50000
#define NEDGES 800000
#define DF 128

#define GBLK 391                 // ceil(50000/128) gemm tiles
#define AGGBLK 6250              // ceil(50000/8) agg blocks (8 warps/block)

// ---------------- device scratch ----------------
__device__ int   g_deg[NNODES];
__device__ int   g_fill[NNODES];
__device__ int   g_ptr[NNODES + 1];
__device__ int   g_csr[NEDGES];
__device__ float g_agg[(size_t)NNODES * DF];
__device__ float g_h[(size_t)NNODES * DF];
__device__ float g_P[(size_t)NNODES * DF];
__device__ float g_BS0[DF * 128];   // Wr0+Ws0
__device__ float g_BS1[DF * 128];
__device__ float g_BS2[DF * 64];
__device__ float g_c0[128];
__device__ float g_c1[128];
__device__ float g_c2[64];

// ---------------- CSR build ----------------
__global__ void zero_kernel() {
    int i = blockIdx.x * blockDim.x + threadIdx.x;
    if (i < NNODES) { g_deg[i] = 0; g_fill[i] = 0; }
}

__global__ void hist_kernel(const int* __restrict__ dst) {
    int e = blockIdx.x * blockDim.x + threadIdx.x;
    if (e < NEDGES) atomicAdd(&g_deg[dst[e]], 1);
}

__global__ void scan_kernel() {
    __shared__ int s[1024];
    int t = threadIdx.x;
    const int CH = (NNODES + 1023) / 1024;
    int start = t * CH;
    int end = min(start + CH, NNODES);
    int local = 0;
    for (int i = start; i < end; i++) local += g_deg[i];
    s[t] = local;
    __syncthreads();
    for (int off = 1; off < 1024; off <<= 1) {
        int v = (t >= off) ? s[t - off] : 0;
        __syncthreads();
        s[t] += v;
        __syncthreads();
    }
    int run = (t == 0) ? 0 : s[t - 1];
    for (int i = start; i < end; i++) { g_ptr[i] = run; run += g_deg[i]; }
    if (end == NNODES) g_ptr[NNODES] = run;
}

__global__ void fill_kernel(const int* __restrict__ src,
                            const int* __restrict__ dst) {
    int e = blockIdx.x * blockDim.x + threadIdx.x;
    if (e < NEDGES) {
        int d = dst[e];
        int pos = g_ptr[d] + atomicAdd(&g_fill[d], 1);
        g_csr[pos] = src[e];
    }
}

// ---------------- combined skip weights: BS = Wr+Ws, c = bl+bs ----------------
__global__ void combine_kernel(const float* __restrict__ Wr, const float* __restrict__ Ws,
                               const float* __restrict__ bl, const float* __restrict__ bs,
                               float* __restrict__ BS, float* __restrict__ bc, int dout) {
    int i = blockIdx.x * blockDim.x + threadIdx.x;
    if (i < DF * dout) BS[i] = Wr[i] + Ws[i];
    if (i < dout) bc[i] = bl[i] + bs[i];
}

// ---------------- packed f32x2 helpers ----------------
__device__ __forceinline__ void ffma2(uint64_t& d, uint64_t a, uint64_t b) {
    asm("fma.rn.f32x2 %0, %1, %2, %0;" : "+l"(d) : "l"(a), "l"(b));
}
__device__ __forceinline__ uint64_t bcast2(float v) {
    uint64_t r;
    asm("mov.b64 %0, {%1, %1};" : "=l"(r) : "f"(v));
    return r;
}

// ======================================================================
// Mixed kernel: blocks [0, GBLK) compute P = X @ BS (K=128 skip GEMM);
// blocks [GBLK, GBLK+AGGBLK) do warp-per-node mean aggregation of X.
// ======================================================================
template <int BN, int TN>
__global__ void __launch_bounds__(256)
mixed_kernel(const float* __restrict__ X, const float* __restrict__ BS,
             float* __restrict__ P, int M) {
    constexpr int BM = 128, BK = 16, TM = 8;
    constexpr int NCH = DF / BK;               // 8
    constexpr int B_F4 = BK * BN / 4 / 256;    // 2 (BN=128) / 1 (BN=64)
    constexpr int TN2 = TN / 2;
    __shared__ float As[BK][BM];
    __shared__ float Bs[BK][BN];

    if (blockIdx.x >= GBLK) {
        // ---------------- aggregation path ----------------
        int node = (blockIdx.x - GBLK) * 8 + (threadIdx.x >> 5);
        int lane = threadIdx.x & 31;
        if (node >= NNODES) return;
        int e0 = g_ptr[node], e1 = g_ptr[node + 1];
        const float4* __restrict__ X4 = (const float4*)X;
        float4 a0 = make_float4(0.f, 0.f, 0.f, 0.f);
        float4 a1 = a0, a2 = a0, a3 = a0;
        int e = e0;
        for (; e + 3 < e1; e += 4) {
            int s0 = g_csr[e], s1 = g_csr[e + 1], s2 = g_csr[e + 2], s3 = g_csr[e + 3];
            float4 v0 = __ldcg(&X4[(size_t)s0 * 32 + lane]);
            float4 v1 = __ldcg(&X4[(size_t)s1 * 32 + lane]);
            float4 v2 = __ldcg(&X4[(size_t)s2 * 32 + lane]);
            float4 v3 = __ldcg(&X4[(size_t)s3 * 32 + lane]);
            a0.x += v0.x; a0.y += v0.y; a0.z += v0.z; a0.w += v0.w;
            a1.x += v1.x; a1.y += v1.y; a1.z += v1.z; a1.w += v1.w;
            a2.x += v2.x; a2.y += v2.y; a2.z += v2.z; a2.w += v2.w;
            a3.x += v3.x; a3.y += v3.y; a3.z += v3.z; a3.w += v3.w;
        }
        for (; e < e1; e++) {
            int s0 = g_csr[e];
            float4 v0 = __ldcg(&X4[(size_t)s0 * 32 + lane]);
            a0.x += v0.x; a0.y += v0.y; a0.z += v0.z; a0.w += v0.w;
        }
        float sc = 1.0f / (float)max(e1 - e0, 1);
        float4 r;
        r.x = (a0.x + a1.x + a2.x + a3.x) * sc;
        r.y = (a0.y + a1.y + a2.y + a3.y) * sc;
        r.z = (a0.z + a1.z + a2.z + a3.z) * sc;
        r.w = (a0.w + a1.w + a2.w + a3.w) * sc;
        ((float4*)g_agg)[(size_t)node * 32 + lane] = r;
        return;
    }

    // ---------------- skip-GEMM path: P = X @ BS ----------------
    int tid = threadIdx.x;
    int m0 = blockIdx.x * BM;
    constexpr int TX = BN / TN;
    int tx = tid % TX;
    int ty = tid / TX;

    uint64_t acc2[TM][TN2];
#pragma unroll
    for (int i = 0; i < TM; i++)
#pragma unroll
        for (int j = 0; j < TN2; j++) acc2[i][j] = 0ull;

    float4 areg[2], breg[B_F4];

    auto fetch = [&](int c) {
        int kc = c * BK;
#pragma unroll
        for (int l = 0; l < 2; l++) {
            int f = tid + l * 256;
            int row = f >> 2;
            int k4 = (f & 3) * 4;
            int m = m0 + row;
            areg[l] = (m < M) ? *(const float4*)(X + (size_t)m * DF + kc + k4)
                              : make_float4(0.f, 0.f, 0.f, 0.f);
        }
#pragma unroll
        for (int l = 0; l < B_F4; l++) {
            int f = tid + l * 256;
            int row = f / (BN / 4);
            int c4 = (f % (BN / 4)) * 4;
            breg[l] = *(const float4*)(BS + (kc + row) * BN + c4);
        }
    };
    auto stage = [&]() {
#pragma unroll
        for (int l = 0; l < 2; l++) {
            int f = tid + l * 256;
            int row = f >> 2;
            int k4 = (f & 3) * 4;
            As[k4 + 0][row] = areg[l].x;
            As[k4 + 1][row] = areg[l].y;
            As[k4 + 2][row] = areg[l].z;
            As[k4 + 3][row] = areg[l].w;
        }
#pragma unroll
        for (int l = 0; l < B_F4; l++) {
            int f = tid + l * 256;
            int row = f / (BN / 4);
            int c4 = (f % (BN / 4)) * 4;
            *(float4*)&Bs[row][c4] = breg[l];
        }
    };

    fetch(0);
#pragma unroll
    for (int c = 0; c < NCH; c++) {
        stage();
        __syncthreads();
        if (c + 1 < NCH) fetch(c + 1);
#pragma unroll
        for (int kk = 0; kk < BK; kk++) {
            float ra[TM];
            uint64_t rb2[TN2];
#pragma unroll
            for (int i = 0; i < TM; i += 4)
                *(float4*)&ra[i] = *(const float4*)&As[kk][ty * TM + i];
#pragma unroll
            for (int j = 0; j < TN2; j += 2) {
                ulonglong2 t = *(const ulonglong2*)&Bs[kk][tx * TN + j * 2];
                rb2[j] = t.x;
                rb2[j + 1] = t.y;
            }
            uint64_t a2[TM];
#pragma unroll
            for (int i = 0; i < TM; i++) a2[i] = bcast2(ra[i]);
#pragma unroll
            for (int i = 0; i < TM; i++)
#pragma unroll
                for (int j = 0; j < TN2; j++) ffma2(acc2[i][j], a2[i], rb2[j]);
        }
        __syncthreads();
    }

#pragma unroll
    for (int i = 0; i < TM; i++) {
        int m = m0 + ty * TM + i;
        if (m < M) {
            const float* accf = (const float*)acc2[i];
#pragma unroll
            for (int j = 0; j < TN; j += 4)
                *(float4*)&P[(size_t)m * BN + tx * TN + j] = *(const float4*)&accf[j];
        }
    }
}

// ======================================================================
// gemm2: C = Aagg @ Wl (K=128) + P + bias (+relu)
// ======================================================================
template <int BN, int TN, bool RELU>
__global__ void __launch_bounds__(256)
gemm2_kernel(const float* __restrict__ A, const float* __restrict__ B,
             const float* __restrict__ P, const float* __restrict__ bias,
             float* __restrict__ C, int M) {
    constexpr int BM = 128, BK = 16, TM = 8;
    constexpr int NCH = DF / BK;               // 8
    constexpr int B_F4 = BK * BN / 4 / 256;
    constexpr int TN2 = TN / 2;
    __shared__ float As[BK][BM];
    __shared__ float Bs[BK][BN];

    int tid = threadIdx.x;
    int m0 = blockIdx.x * BM;
    constexpr int TX = BN / TN;
    int tx = tid % TX;
    int ty = tid / TX;

    uint64_t acc2[TM][TN2];
#pragma unroll
    for (int i = 0; i < TM; i++)
#pragma unroll
        for (int j = 0; j < TN2; j++) acc2[i][j] = 0ull;

    float4 areg[2], breg[B_F4];

    auto fetch = [&](int c) {
        int kc = c * BK;
#pragma unroll
        for (int l = 0; l < 2; l++) {
            int f = tid + l * 256;
            int row = f >> 2;
            int k4 = (f & 3) * 4;
            int m = m0 + row;
            areg[l] = (m < M) ? *(const float4*)(A + (size_t)m * DF + kc + k4)
                              : make_float4(0.f, 0.f, 0.f, 0.f);
        }
#pragma unroll
        for (int l = 0; l < B_F4; l++) {
            int f = tid + l * 256;
            int row = f / (BN / 4);
            int c4 = (f % (BN / 4)) * 4;
            breg[l] = *(const float4*)(B + (kc + row) * BN + c4);
        }
    };
    auto stage = [&]() {
#pragma unroll
        for (int l = 0; l < 2; l++) {
            int f = tid + l * 256;
            int row = f >> 2;
            int k4 = (f & 3) * 4;
            As[k4 + 0][row] = areg[l].x;
            As[k4 + 1][row] = areg[l].y;
            As[k4 + 2][row] = areg[l].z;
            As[k4 + 3][row] = areg[l].w;
        }
#pragma unroll
        for (int l = 0; l < B_F4; l++) {
            int f = tid + l * 256;
            int row = f / (BN / 4);
            int c4 = (f % (BN / 4)) * 4;
            *(float4*)&Bs[row][c4] = breg[l];
        }
    };

    fetch(0);
#pragma unroll
    for (int c = 0; c < NCH; c++) {
        stage();
        __syncthreads();
        if (c + 1 < NCH) fetch(c + 1);
#pragma unroll
        for (int kk = 0; kk < BK; kk++) {
            float ra[TM];
            uint64_t rb2[TN2];
#pragma unroll
            for (int i = 0; i < TM; i += 4)
                *(float4*)&ra[i] = *(const float4*)&As[kk][ty * TM + i];
#pragma unroll
            for (int j = 0; j < TN2; j += 2) {
                ulonglong2 t = *(const ulonglong2*)&Bs[kk][tx * TN + j * 2];
                rb2[j] = t.x;
                rb2[j + 1] = t.y;
            }
            uint64_t a2[TM];
#pragma unroll
            for (int i = 0; i < TM; i++) a2[i] = bcast2(ra[i]);
#pragma unroll
            for (int i = 0; i < TM; i++)
#pragma unroll
                for (int j = 0; j < TN2; j++) ffma2(acc2[i][j], a2[i], rb2[j]);
        }
        __syncthreads();
    }

#pragma unroll
    for (int i = 0; i < TM; i++) {
        int m = m0 + ty * TM + i;
        if (m < M) {
            const float* accf = (const float*)acc2[i];
#pragma unroll
            for (int j = 0; j < TN; j += 4) {
                float4 p = *(const float4*)&P[(size_t)m * BN + tx * TN + j];
                float4 o;
                o.x = accf[j + 0] + p.x + bias[tx * TN + j + 0];
                o.y = accf[j + 1] + p.y + bias[tx * TN + j + 1];
                o.z = accf[j + 2] + p.z + bias[tx * TN + j + 2];
                o.w = accf[j + 3] + p.w + bias[tx * TN + j + 3];
                if (RELU) {
                    o.x = fmaxf(o.x, 0.f);
                    o.y = fmaxf(o.y, 0.f);
                    o.z = fmaxf(o.z, 0.f);
                    o.w = fmaxf(o.w, 0.f);
                }
                *(float4*)&C[(size_t)m * BN + tx * TN + j] = o;
            }
        }
    }
}

// ---------------- launch ----------------
extern "C" void kernel_launch(void* const* d_in, const int* in_sizes, int n_in,
                              void* d_out, int out_size) {
    const float* x = (const float*)d_in[0];
    const int* ei = (const int*)d_in[1];       // int32 (JAX canonicalized)
    const float* Wl0 = (const float*)d_in[4];
    const float* bl0 = (const float*)d_in[5];
    const float* Wr0 = (const float*)d_in[6];
    const float* Ws0 = (const float*)d_in[7];
    const float* bs0 = (const float*)d_in[8];
    const float* Wl1 = (const float*)d_in[9];
    const float* bl1 = (const float*)d_in[10];
    const float* Wr1 = (const float*)d_in[11];
    const float* Ws1 = (const float*)d_in[12];
    const float* bs1 = (const float*)d_in[13];
    const float* Wl2 = (const float*)d_in[14];
    const float* bl2 = (const float*)d_in[15];
    const float* Wr2 = (const float*)d_in[16];
    const float* Ws2 = (const float*)d_in[17];
    const float* bs2 = (const float*)d_in[18];

    const int* src = ei;
    const int* dst = ei + NEDGES;

    float *agg, *h, *P, *BS0, *BS1, *BS2, *c0, *c1, *c2;
    cudaGetSymbolAddress((void**)&agg, g_agg);
    cudaGetSymbolAddress((void**)&h, g_h);
    cudaGetSymbolAddress((void**)&P, g_P);
    cudaGetSymbolAddress((void**)&BS0, g_BS0);
    cudaGetSymbolAddress((void**)&BS1, g_BS1);
    cudaGetSymbolAddress((void**)&BS2, g_BS2);
    cudaGetSymbolAddress((void**)&c0, g_c0);
    cudaGetSymbolAddress((void**)&c1, g_c1);
    cudaGetSymbolAddress((void**)&c2, g_c2);

    // CSR build
    zero_kernel<<<(NNODES + 255) / 256, 256>>>();
    hist_kernel<<<(NEDGES + 255) / 256, 256>>>(dst);
    scan_kernel<<<1, 1024>>>();
    fill_kernel<<<(NEDGES + 255) / 256, 256>>>(src, dst);

    // skip-weight fusion (Wl used directly)
    combine_kernel<<<(DF * 128 + 255) / 256, 256>>>(Wr0, Ws0, bl0, bs0, BS0, c0, 128);
    combine_kernel<<<(DF * 128 + 255) / 256, 256>>>(Wr1, Ws1, bl1, bs1, BS1, c1, 128);
    combine_kernel<<<(DF * 64 + 255) / 256, 256>>>(Wr2, Ws2, bl2, bs2, BS2, c2, 64);

    int mixedGrid = GBLK + AGGBLK;

    // layer 0
    mixed_kernel<128, 8><<<mixedGrid, 256>>>(x, BS0, P, NNODES);
    gemm2_kernel<128, 8, true><<<GBLK, 256>>>(agg, Wl0, P, c0, h, NNODES);
    // layer 1
    mixed_kernel<128, 8><<<mixedGrid, 256>>>(h, BS1, P, NNODES);
    gemm2_kernel<128, 8, true><<<GBLK, 256>>>(agg, Wl1, P, c1, h, NNODES);
    // layer 2
    mixed_kernel<64, 4><<<mixedGrid, 256>>>(h, BS2, P, NNODES);
    gemm2_kernel<64, 4, false><<<GBLK, 256>>>(agg, Wl2, P, c2, (float*)d_out, NNODES);
}

// round 7
// speedup vs baseline: 1.2845x; 1.2845x over previous
#include <cuda_runtime.h>
#include <cstdint>

#define NNODES 50000
#define NEDGES 800000
#define DF 128          // per-half feature dim (agg | x)
#define KTOT 256        // concatenated K

// ---------------- device scratch ----------------
__device__ int   g_deg[NNODES];
__device__ int   g_fill[NNODES];
__device__ int   g_ptr[NNODES + 1];
__device__ int   g_csr[NEDGES];
__device__ float g_agg[(size_t)NNODES * DF];
__device__ float g_h[(size_t)NNODES * DF];
__device__ float g_B0[KTOT * 128];
__device__ float g_B1[KTOT * 128];
__device__ float g_B2[KTOT * 64];
__device__ float g_c0[128];
__device__ float g_c1[128];
__device__ float g_c2[64];

// ---------------- CSR build ----------------
__global__ void zero_kernel() {
    int i = blockIdx.x * blockDim.x + threadIdx.x;
    if (i < NNODES) { g_deg[i] = 0; g_fill[i] = 0; }
}

__global__ void hist_kernel(const int* __restrict__ dst) {
    int e = blockIdx.x * blockDim.x + threadIdx.x;
    if (e < NEDGES) atomicAdd(&g_deg[dst[e]], 1);
}

__global__ void scan_kernel() {
    __shared__ int s[1024];
    int t = threadIdx.x;
    const int CH = (NNODES + 1023) / 1024;
    int start = t * CH;
    int end = min(start + CH, NNODES);
    int local = 0;
    for (int i = start; i < end; i++) local += g_deg[i];
    s[t] = local;
    __syncthreads();
    for (int off = 1; off < 1024; off <<= 1) {
        int v = (t >= off) ? s[t - off] : 0;
        __syncthreads();
        s[t] += v;
        __syncthreads();
    }
    int run = (t == 0) ? 0 : s[t - 1];
    for (int i = start; i < end; i++) { g_ptr[i] = run; run += g_deg[i]; }
    if (end == NNODES) g_ptr[NNODES] = run;
}

__global__ void fill_kernel(const int* __restrict__ src,
                            const int* __restrict__ dst) {
    int e = blockIdx.x * blockDim.x + threadIdx.x;
    if (e < NEDGES) {
        int d = dst[e];
        int pos = g_ptr[d] + atomicAdd(&g_fill[d], 1);
        g_csr[pos] = src[e];
    }
}

// ---------------- combined weights: Bcat = [Wl ; Wr+Ws], c = bl+bs ----------------
__global__ void combine_kernel(const float* __restrict__ Wl, const float* __restrict__ Wr,
                               const float* __restrict__ Ws, const float* __restrict__ bl,
                               const float* __restrict__ bs, float* __restrict__ Bc,
                               float* __restrict__ bc, int dout) {
    int i = blockIdx.x * blockDim.x + threadIdx.x;
    if (i < KTOT * dout) {
        int k = i / dout, n = i % dout;
        Bc[i] = (k < DF) ? Wl[k * dout + n]
                         : Wr[(k - DF) * dout + n] + Ws[(k - DF) * dout + n];
    }
    if (i < dout) bc[i] = bl[i] + bs[i];
}

// ---------------- mean aggregation: warp per node, unroll 8 ----------------
__global__ void agg_kernel(const float* __restrict__ X) {
    int warp = (blockIdx.x * blockDim.x + threadIdx.x) >> 5;
    int lane = threadIdx.x & 31;
    if (warp >= NNODES) return;
    int e0 = g_ptr[warp], e1 = g_ptr[warp + 1];
    const float4* __restrict__ X4 = (const float4*)X;
    float4 a0 = make_float4(0.f, 0.f, 0.f, 0.f);
    float4 a1 = a0, a2 = a0, a3 = a0;
    int e = e0;
    for (; e + 7 < e1; e += 8) {
        int s0 = g_csr[e],     s1 = g_csr[e + 1], s2 = g_csr[e + 2], s3 = g_csr[e + 3];
        int s4 = g_csr[e + 4], s5 = g_csr[e + 5], s6 = g_csr[e + 6], s7 = g_csr[e + 7];
        float4 v0 = X4[(size_t)s0 * 32 + lane];
        float4 v1 = X4[(size_t)s1 * 32 + lane];
        float4 v2 = X4[(size_t)s2 * 32 + lane];
        float4 v3 = X4[(size_t)s3 * 32 + lane];
        float4 v4 = X4[(size_t)s4 * 32 + lane];
        float4 v5 = X4[(size_t)s5 * 32 + lane];
        float4 v6 = X4[(size_t)s6 * 32 + lane];
        float4 v7 = X4[(size_t)s7 * 32 + lane];
        a0.x += v0.x; a0.y += v0.y; a0.z += v0.z; a0.w += v0.w;
        a1.x += v1.x; a1.y += v1.y; a1.z += v1.z; a1.w += v1.w;
        a2.x += v2.x; a2.y += v2.y; a2.z += v2.z; a2.w += v2.w;
        a3.x += v3.x; a3.y += v3.y; a3.z += v3.z; a3.w += v3.w;
        a0.x += v4.x; a0.y += v4.y; a0.z += v4.z; a0.w += v4.w;
        a1.x += v5.x; a1.y += v5.y; a1.z += v5.z; a1.w += v5.w;
        a2.x += v6.x; a2.y += v6.y; a2.z += v6.z; a2.w += v6.w;
        a3.x += v7.x; a3.y += v7.y; a3.z += v7.z; a3.w += v7.w;
    }
    for (; e < e1; e++) {
        int s0 = g_csr[e];
        float4 v0 = X4[(size_t)s0 * 32 + lane];
        a0.x += v0.x; a0.y += v0.y; a0.z += v0.z; a0.w += v0.w;
    }
    int cnt = e1 - e0;
    float sc = 1.0f / (float)max(cnt, 1);
    float4 r;
    r.x = (a0.x + a1.x + a2.x + a3.x) * sc;
    r.y = (a0.y + a1.y + a2.y + a3.y) * sc;
    r.z = (a0.z + a1.z + a2.z + a3.z) * sc;
    r.w = (a0.w + a1.w + a2.w + a3.w) * sc;
    ((float4*)g_agg)[(size_t)warp * 32 + lane] = r;
}

// ---------------- packed f32x2 FMA helper ----------------
__device__ __forceinline__ void ffma2(uint64_t& d, uint64_t a, uint64_t b) {
    asm("fma.rn.f32x2 %0, %1, %2, %0;" : "+l"(d) : "l"(a), "l"(b));
}
__device__ __forceinline__ uint64_t bcast2(float v) {
    uint64_t r;
    asm("mov.b64 %0, {%1, %1};" : "=l"(r) : "f"(v));
    return r;
}

// ---------------- fused SGEMM (f32x2): C = [Aagg | Ax] @ Bcat + bias (opt. relu) ----------------
template <int BN, int TN, bool RELU>
__global__ void __launch_bounds__(256)
gemm_kernel(const float* __restrict__ Aagg, const float* __restrict__ Ax,
            const float* __restrict__ B, const float* __restrict__ bias,
            float* __restrict__ C, int M) {
    constexpr int BM = 128, BK = 16, TM = 8;
    constexpr int NCH = KTOT / BK;             // 16 chunks
    constexpr int A_F4 = BM * BK / 4 / 256;    // 2
    constexpr int B_F4 = BK * BN / 4 / 256;    // 2 (BN=128) or 1 (BN=64)
    constexpr int TN2 = TN / 2;
    __shared__ float As[BK][BM];
    __shared__ float Bs[BK][BN];

    int tid = threadIdx.x;
    int m0 = blockIdx.x * BM;
    constexpr int TX = BN / TN;                // 16
    int tx = tid % TX;
    int ty = tid / TX;                         // 0..15

    uint64_t acc2[TM][TN2];
#pragma unroll
    for (int i = 0; i < TM; i++)
#pragma unroll
        for (int j = 0; j < TN2; j++) acc2[i][j] = 0ull;

    float4 areg[A_F4], breg[B_F4];

    auto fetch = [&](int c) {
        int kc = c * BK;
#pragma unroll
        for (int l = 0; l < A_F4; l++) {
            int f = tid + l * 256;
            int row = f >> 2;                  // 0..127
            int k4 = (f & 3) * 4;              // 0,4,8,12
            int m = m0 + row;
            int kg = kc + k4;
            const float* Ap = (kg < DF) ? (Aagg + (size_t)m * DF + kg)
                                        : (Ax + (size_t)m * DF + (kg - DF));
            areg[l] = (m < M) ? *(const float4*)Ap : make_float4(0.f, 0.f, 0.f, 0.f);
        }
#pragma unroll
        for (int l = 0; l < B_F4; l++) {
            int f = tid + l * 256;
            int row = f / (BN / 4);
            int c4 = (f % (BN / 4)) * 4;
            breg[l] = *(const float4*)(B + (kc + row) * BN + c4);
        }
    };
    auto stage = [&]() {
#pragma unroll
        for (int l = 0; l < A_F4; l++) {
            int f = tid + l * 256;
            int row = f >> 2;
            int k4 = (f & 3) * 4;
            As[k4 + 0][row] = areg[l].x;
            As[k4 + 1][row] = areg[l].y;
            As[k4 + 2][row] = areg[l].z;
            As[k4 + 3][row] = areg[l].w;
        }
#pragma unroll
        for (int l = 0; l < B_F4; l++) {
            int f = tid + l * 256;
            int row = f / (BN / 4);
            int c4 = (f % (BN / 4)) * 4;
            *(float4*)&Bs[row][c4] = breg[l];
        }
    };

    fetch(0);
#pragma unroll
    for (int c = 0; c < NCH; c++) {
        stage();
        __syncthreads();
        if (c + 1 < NCH) fetch(c + 1);  // LDGs in flight under compute
#pragma unroll
        for (int kk = 0; kk < BK; kk++) {
            float ra[TM];
            uint64_t rb2[TN2];
#pragma unroll
            for (int i = 0; i < TM; i += 4)
                *(float4*)&ra[i] = *(const float4*)&As[kk][ty * TM + i];
#pragma unroll
            for (int j = 0; j < TN2; j += 2) {
                ulonglong2 t = *(const ulonglong2*)&Bs[kk][tx * TN + j * 2];
                rb2[j] = t.x;
                rb2[j + 1] = t.y;
            }
            uint64_t a2[TM];
#pragma unroll
            for (int i = 0; i < TM; i++) a2[i] = bcast2(ra[i]);
#pragma unroll
            for (int i = 0; i < TM; i++)
#pragma unroll
                for (int j = 0; j < TN2; j++) ffma2(acc2[i][j], a2[i], rb2[j]);
        }
        __syncthreads();
    }

#pragma unroll
    for (int i = 0; i < TM; i++) {
        int m = m0 + ty * TM + i;
        if (m < M) {
            const float* accf = (const float*)acc2[i];
#pragma unroll
            for (int j = 0; j < TN; j += 4) {
                float4 o;
                o.x = accf[j + 0] + bias[tx * TN + j + 0];
                o.y = accf[j + 1] + bias[tx * TN + j + 1];
                o.z = accf[j + 2] + bias[tx * TN + j + 2];
                o.w = accf[j + 3] + bias[tx * TN + j + 3];
                if (RELU) {
                    o.x = fmaxf(o.x, 0.f);
                    o.y = fmaxf(o.y, 0.f);
                    o.z = fmaxf(o.z, 0.f);
                    o.w = fmaxf(o.w, 0.f);
                }
                *(float4*)&C[(size_t)m * BN + tx * TN + j] = o;
            }
        }
    }
}

// ---------------- launch ----------------
extern "C" void kernel_launch(void* const* d_in, const int* in_sizes, int n_in,
                              void* d_out, int out_size) {
    const float* x = (const float*)d_in[0];
    const int* ei = (const int*)d_in[1];       // int32 (JAX canonicalized)
    const float* Wl0 = (const float*)d_in[4];
    const float* bl0 = (const float*)d_in[5];
    const float* Wr0 = (const float*)d_in[6];
    const float* Ws0 = (const float*)d_in[7];
    const float* bs0 = (const float*)d_in[8];
    const float* Wl1 = (const float*)d_in[9];
    const float* bl1 = (const float*)d_in[10];
    const float* Wr1 = (const float*)d_in[11];
    const float* Ws1 = (const float*)d_in[12];
    const float* bs1 = (const float*)d_in[13];
    const float* Wl2 = (const float*)d_in[14];
    const float* bl2 = (const float*)d_in[15];
    const float* Wr2 = (const float*)d_in[16];
    const float* Ws2 = (const float*)d_in[17];
    const float* bs2 = (const float*)d_in[18];

    const int* src = ei;
    const int* dst = ei + NEDGES;

    float *agg, *h, *B0, *B1, *B2, *c0, *c1, *c2;
    cudaGetSymbolAddress((void**)&agg, g_agg);
    cudaGetSymbolAddress((void**)&h, g_h);
    cudaGetSymbolAddress((void**)&B0, g_B0);
    cudaGetSymbolAddress((void**)&B1, g_B1);
    cudaGetSymbolAddress((void**)&B2, g_B2);
    cudaGetSymbolAddress((void**)&c0, g_c0);
    cudaGetSymbolAddress((void**)&c1, g_c1);
    cudaGetSymbolAddress((void**)&c2, g_c2);

    // CSR build
    zero_kernel<<<(NNODES + 255) / 256, 256>>>();
    hist_kernel<<<(NEDGES + 255) / 256, 256>>>(dst);
    scan_kernel<<<1, 1024>>>();
    fill_kernel<<<(NEDGES + 255) / 256, 256>>>(src, dst);

    // weight fusion
    combine_kernel<<<(KTOT * 128 + 255) / 256, 256>>>(Wl0, Wr0, Ws0, bl0, bs0, B0, c0, 128);
    combine_kernel<<<(KTOT * 128 + 255) / 256, 256>>>(Wl1, Wr1, Ws1, bl1, bs1, B1, c1, 128);
    combine_kernel<<<(KTOT * 64 + 255) / 256, 256>>>(Wl2, Wr2, Ws2, bl2, bs2, B2, c2, 64);

    int aggGrid = (NNODES * 32 + 255) / 256;   // warp per node
    int gemmGrid = (NNODES + 127) / 128;

    // layer 0: h = relu([agg(x) | x] @ B0 + c0)
    agg_kernel<<<aggGrid, 256>>>(x);
    gemm_kernel<128, 8, true><<<gemmGrid, 256>>>(agg, x, B0, c0, h, NNODES);
    // layer 1: h = relu([agg(h) | h] @ B1 + c1)
    agg_kernel<<<aggGrid, 256>>>(h);
    gemm_kernel<128, 8, true><<<gemmGrid, 256>>>(agg, h, B1, c1, h, NNODES);
    // layer 2: out = [agg(h) | h] @ B2 + c2
    agg_kernel<<<aggGrid, 256>>>(h);
    gemm_kernel<64, 4, false><<<gemmGrid, 256>>>(agg, h, B2, c2, (float*)d_out, NNODES);
}